// round 10
// baseline (speedup 1.0000x reference)
#include <cuda_runtime.h>
#include <cstdint>

// Problem constants
#define B_   4
#define S_   2048
#define D_   768
#define NH_  4
#define DH_  192
#define KC_  4
#define EPS_ 1e-5f

// Scratch (device globals; no allocation allowed)
__device__ float g_xconv[B_ * S_ * D_];            // 25 MB
__device__ float g_G[4 * B_ * S_ * D_];            // 100 MB
__device__ float g_yraw[B_ * S_ * D_];             // 25 MB

// ---------------------------------------------------------------------------
// Kernel 1: causal depthwise conv1d + swish
// ---------------------------------------------------------------------------
__global__ __launch_bounds__(256) void conv_swish_kernel(
    const float* __restrict__ x, const float* __restrict__ ck,
    const float* __restrict__ cb)
{
    int idx = blockIdx.x * 256 + threadIdx.x;
    if (idx >= B_ * S_ * D_) return;
    int d = idx % D_;
    int s = (idx / D_) & (S_ - 1);
    float acc = cb[d];
    const float* xp = x + idx;
#pragma unroll
    for (int j = 0; j < KC_; j++) {
        int ss = s - (KC_ - 1) + j;
        if (ss >= 0) acc += ck[j * D_ + d] * xp[(j - (KC_ - 1)) * D_];
    }
    g_xconv[idx] = acc / (1.f + __expf(-acc));
}

// ---------------------------------------------------------------------------
// Kernel 2: headwise gate GEMMs (known good).
// ---------------------------------------------------------------------------
__global__ __launch_bounds__(256) void gate_gemm_kernel(
    const float* __restrict__ x,
    const float* __restrict__ Wi, const float* __restrict__ Wf,
    const float* __restrict__ Wz, const float* __restrict__ Wo)
{
    const int gz = blockIdx.z;
    const int g = gz >> 2;
    const int h = gz & 3;
    const float* A = (g < 2) ? g_xconv : x;
    const float* W = (g == 0) ? Wi : (g == 1) ? Wf : (g == 2) ? Wz : Wo;
    W += (size_t)h * DH_ * DH_;

    const int n0 = blockIdx.x * 64;
    const int m0 = blockIdx.y * 64;

    __shared__ __align__(16) float As[16][68];  // [k][m]
    __shared__ __align__(16) float Bs[16][68];  // [k][e]

    const int tid = threadIdx.x;
    const int tn = tid & 15;
    const int tm = tid >> 4;

    float acc[4][4] = {};

    for (int k0 = 0; k0 < DH_; k0 += 16) {
#pragma unroll
        for (int i = 0; i < 4; i++) {
            int lin = tid + i * 256;
            int r = lin >> 4, cc = lin & 15;
            As[cc][r] = A[(size_t)(m0 + r) * D_ + h * DH_ + k0 + cc];
        }
#pragma unroll
        for (int i = 0; i < 4; i++) {
            int lin = tid + i * 256;
            int r = lin >> 6, cc = lin & 63;
            Bs[r][cc] = W[(size_t)(k0 + r) * DH_ + n0 + cc];
        }
        __syncthreads();
#pragma unroll
        for (int kk = 0; kk < 16; kk++) {
            float4 av = *(const float4*)&As[kk][tm * 4];
            float4 bv = *(const float4*)&Bs[kk][tn * 4];
            acc[0][0] += av.x * bv.x; acc[0][1] += av.x * bv.y;
            acc[0][2] += av.x * bv.z; acc[0][3] += av.x * bv.w;
            acc[1][0] += av.y * bv.x; acc[1][1] += av.y * bv.y;
            acc[1][2] += av.y * bv.z; acc[1][3] += av.y * bv.w;
            acc[2][0] += av.z * bv.x; acc[2][1] += av.z * bv.y;
            acc[2][2] += av.z * bv.z; acc[2][3] += av.z * bv.w;
            acc[3][0] += av.w * bv.x; acc[3][1] += av.w * bv.y;
            acc[3][2] += av.w * bv.z; acc[3][3] += av.w * bv.w;
        }
        __syncthreads();
    }

#pragma unroll
    for (int i = 0; i < 4; i++) {
        int mm = m0 + tm * 4 + i;
        int bb = mm >> 11;
        int ss = mm & (S_ - 1);
        float4 v = make_float4(acc[i][0], acc[i][1], acc[i][2], acc[i][3]);
        *(float4*)&g_G[((size_t)(bb * NH_ + h) * S_ + ss) * D_ + g * DH_ + n0 + tn * 4] = v;
    }
}

// ---------------------------------------------------------------------------
// Kernel 3: sequential sLSTM scan — 8-CTA cluster + st.async transactions.
// One cluster of 8 CTAs per (b,h) chain; CTA rank q owns e in [24q, 24q+24).
// 192 threads, lane-pair d-split:
//   p = tid/2 (0..95): matvec column -> gate gp = p/24, el = p%24, e = 24q+el
//   ph = tid&1: d-half [ph*96, ph*96+96); pair combines via one shfl.xor.
// Gate tail replicated: every thread carries state (c,n,m) for column
// cl = tid%24 (identical fp ops across the 8 replicas -> deterministic),
// then sends hn[cl] to rank tid/24 via ONE st.async (4B tx). Each CTA's
// mbarrier (count=1) expects 8 ranks x 24 x 4B = 768B per phase.
// Same R8 protocol otherwise: tid0 arms expect_tx after the wait; WAR safety
// from the double buffer + the single __syncthreads between matvec reads and
// the sends.
// ---------------------------------------------------------------------------
__device__ __forceinline__ uint32_t smem_u32(const void* p) {
    uint32_t a;
    asm("{ .reg .u64 t; cvta.to.shared.u64 t, %1; cvt.u32.u64 %0, t; }"
        : "=r"(a) : "l"(p));
    return a;
}

#define CLUSTER_SYNC_() do { \
    asm volatile("barrier.cluster.arrive.aligned;" ::: "memory"); \
    asm volatile("barrier.cluster.wait.aligned;"   ::: "memory"); \
} while (0)

__device__ __forceinline__ void mbar_wait_acq(uint32_t addr, uint32_t parity) {
    uint32_t done;
    asm volatile("{\n\t.reg .pred p;\n\t"
        "mbarrier.try_wait.parity.acquire.cluster.shared::cta.b64 p, [%1], %2;\n\t"
        "selp.b32 %0, 1, 0, p;\n\t}"
        : "=r"(done) : "r"(addr), "r"(parity) : "memory");
    if (!done) {
        asm volatile("{\n\t.reg .pred P1;\n\t"
            "WL_%=:\n\t"
            "mbarrier.try_wait.parity.acquire.cluster.shared::cta.b64 P1, [%0], %1, 0x989680;\n\t"
            "@P1 bra.uni WD_%=;\n\t"
            "bra.uni WL_%=;\n\t"
            "WD_%=:\n\t}"
            :: "r"(addr), "r"(parity) : "memory");
    }
}

#define CL_   8                      // cluster size
#define EPC_  (DH_ / CL_)            // 24 e-columns per CTA
#define TX_BYTES_ (DH_ * 4)          // 768: full h per phase

__global__ void __cluster_dims__(CL_, 1, 1) __launch_bounds__(192, 1)
slstm_scan_kernel(const float* __restrict__ R, const float* __restrict__ cell_bias)
{
    __shared__ __align__(16) float hbuf[2][DH_];
    __shared__ float spre[4 * EPC_];   // i, f, tanh(z), sigmoid(o) for local 24 cols
    __shared__ __align__(8) unsigned long long mbar;

    const int tid   = threadIdx.x;
    const int chain = blockIdx.x / CL_;     // 0..15
    const int q     = blockIdx.x % CL_;     // cluster rank 0..7
    const int b     = chain >> 2;
    const int h     = chain & 3;

    // Matvec mapping (lane pairs).
    const int p     = tid >> 1;             // 0..95: column index
    const int ph    = tid & 1;              // d-half
    const int gp    = p / EPC_;             // gate of matvec column
    const int el    = p % EPC_;             // local e of matvec column
    const int ecol  = q * EPC_ + el;        // global e of matvec column

    // Gate-tail / send mapping (replicated state).
    const int cl    = tid % EPC_;           // local column for state
    const int srk   = tid / EPC_;           // destination rank for send

    // Load this thread's half-column of R: 48 packed f32x2 pairs.
    unsigned long long r2[48];
    {
        const float* Rcol = R + ((size_t)(gp * NH_ + h)) * DH_ * DH_
                              + (size_t)(ph * 96) * DH_ + ecol;
#pragma unroll
        for (int j = 0; j < 48; j++) {
            float lo = Rcol[(2 * j) * DH_];
            float hi = Rcol[(2 * j + 1) * DH_];
            asm("mov.b64 %0, {%1, %2};" : "=l"(r2[j]) : "f"(lo), "f"(hi));
        }
    }
    const float cbias = cell_bias[gp * D_ + h * DH_ + ecol];

    // G stream for the matvec column (lane pairs load the same address: broadcast).
    const float* Gp = g_G + ((size_t)(b * NH_ + h)) * S_ * D_ + gp * DH_ + ecol;
    // Y output for the state column (threads 0..23 write).
    float* Yp = g_yraw + (size_t)b * S_ * D_ + h * DH_ + q * EPC_ + cl;

    const uint32_t hb_base = smem_u32(&hbuf[0][0]);
    const uint32_t mb_addr = smem_u32(&mbar);

    hbuf[0][tid] = 0.f;
    hbuf[1][tid] = 0.f;
    if (tid == 0) {
        asm volatile("mbarrier.init.shared.b64 [%0], %1;"
                     :: "r"(mb_addr), "r"(1) : "memory");
        asm volatile("mbarrier.arrive.expect_tx.shared.b64 _, [%0], %1;"
                     :: "r"(mb_addr), "r"(TX_BYTES_) : "memory");
    }
    __syncthreads();
    CLUSTER_SYNC_();   // hbuf + armed mbarrier visible cluster-wide (once)

    // Remote hbuf/mbarrier addresses for this thread's destination rank only.
    uint32_t rhb_s, rmb_s;
    asm("mapa.shared::cluster.u32 %0, %1, %2;" : "=r"(rhb_s) : "r"(hb_base), "r"(srk));
    asm("mapa.shared::cluster.u32 %0, %1, %2;" : "=r"(rmb_s) : "r"(mb_addr), "r"(srk));

    float c = 0.f, n = 0.f, m = 0.f;

    // 2-deep G prefetch ring.
    float gbuf0 = Gp[0];
    float gbuf1 = Gp[D_];

    for (int t = 0; t < S_; ++t) {
        float gnn = (t + 2 < S_) ? Gp[(size_t)(t + 2) * D_] : 0.f;

        if (t > 0) {
            mbar_wait_acq(mb_addr, (uint32_t)((t - 1) & 1));
            if (tid == 0 && t <= S_ - 2) {
                asm volatile("mbarrier.arrive.expect_tx.shared.b64 _, [%0], %1;"
                             :: "r"(mb_addr), "r"(TX_BYTES_) : "memory");
            }
        }

        // Half-matvec: partial[ecol] over d in [ph*96, ph*96+96).
        const ulonglong2* h128 = (const ulonglong2*)&hbuf[t & 1][ph * 96];
        unsigned long long a[4] = {0ull, 0ull, 0ull, 0ull};
#pragma unroll
        for (int jj = 0; jj < 24; jj++) {
            ulonglong2 hv = h128[jj];
            asm("fma.rn.f32x2 %0, %1, %2, %0;"
                : "+l"(a[(2 * jj) & 3]) : "l"(hv.x), "l"(r2[2 * jj]));
            asm("fma.rn.f32x2 %0, %1, %2, %0;"
                : "+l"(a[(2 * jj + 1) & 3]) : "l"(hv.y), "l"(r2[2 * jj + 1]));
        }
        float l0, h0, l1, h1, l2, h2, l3, h3;
        asm("mov.b64 {%0, %1}, %2;" : "=f"(l0), "=f"(h0) : "l"(a[0]));
        asm("mov.b64 {%0, %1}, %2;" : "=f"(l1), "=f"(h1) : "l"(a[1]));
        asm("mov.b64 {%0, %1}, %2;" : "=f"(l2), "=f"(h2) : "l"(a[2]));
        asm("mov.b64 {%0, %1}, %2;" : "=f"(l3), "=f"(h3) : "l"(a[3]));
        float rpart = ((l0 + h0) + (l1 + h1)) + ((l2 + h2) + (l3 + h3));
        // Pair combine: lane ph gets the other half; both lanes end with full dot.
        float rec = rpart + __shfl_xor_sync(0xFFFFFFFFu, rpart, 1);

        // Per-gate nonlinearity in parallel BEFORE the sync.
        float pre = rec + gbuf0 + cbias;
        float sv;
        if (gp == 2)      sv = tanhf(pre);
        else if (gp == 3) sv = __fdividef(1.f, 1.f + __expf(-pre));
        else              sv = pre;
        if (ph == 0) spre[p] = sv;
        __syncthreads();   // spre ready; all hbuf[t&1] reads complete

        // Replicated gate tail: every thread updates state for column cl.
        {
            float i_ = spre[cl];
            float f_ = spre[EPC_ + cl];
            float tz = spre[2 * EPC_ + cl];
            float so = spre[3 * EPC_ + cl];
            float mn = fmaxf(f_ + m, i_);
            float ia = __expf(i_ - mn);
            float fa = __expf(f_ + m - mn);
            c = fa * c + ia * tz;
            n = fa * n + ia;
            m = mn;
            float hn = __fdividef(c, n) * so;

            if (tid < EPC_) Yp[(size_t)t * D_] = hn;

            if (t < S_ - 1) {
                // One send per thread: hn[cl] -> rank srk's hbuf[(t+1)&1][24q+cl].
                uint32_t off = (uint32_t)((((t + 1) & 1) * DH_ + q * EPC_ + cl) * 4);
                uint32_t hv; asm("mov.b32 %0, %1;" : "=r"(hv) : "f"(hn));
                asm volatile(
                    "st.async.shared::cluster.mbarrier::complete_tx::bytes.b32 [%0], %1, [%2];"
                    :: "r"(rhb_s + off), "r"(hv), "r"(rmb_s) : "memory");
            }
        }

        gbuf0 = gbuf1;
        gbuf1 = gnn;
    }

    CLUSTER_SYNC_();   // no CTA exits while peers might still address its smem
}

// ---------------------------------------------------------------------------
// Kernel 4: multi-head layernorm over DH per (b,s,h) row.
// ---------------------------------------------------------------------------
__global__ __launch_bounds__(192) void mh_layernorm_kernel(
    const float* __restrict__ gn_scale, float* __restrict__ out)
{
    const int h  = blockIdx.x & (NH_ - 1);
    const int bs = blockIdx.x >> 2;
    const int base = bs * D_ + h * DH_;
    const int tid = threadIdx.x;

    float v = g_yraw[base + tid];
    float s1 = v, s2 = v * v;
#pragma unroll
    for (int o = 16; o; o >>= 1) {
        s1 += __shfl_xor_sync(0xFFFFFFFFu, s1, o);
        s2 += __shfl_xor_sync(0xFFFFFFFFu, s2, o);
    }
    __shared__ float r1[6], r2s[6];
    int w = tid >> 5;
    if ((tid & 31) == 0) { r1[w] = s1; r2s[w] = s2; }
    __syncthreads();
    float t1 = 0.f, t2 = 0.f;
#pragma unroll
    for (int i = 0; i < 6; i++) { t1 += r1[i]; t2 += r2s[i]; }
    const float inv = 1.f / (float)DH_;
    float mu  = t1 * inv;
    float var = t2 * inv - mu * mu;
    float rs  = rsqrtf(var + EPS_);
    out[base + tid] = (v - mu) * rs * gn_scale[h * DH_ + tid];
}

// ---------------------------------------------------------------------------
// Launch
// ---------------------------------------------------------------------------
extern "C" void kernel_launch(void* const* d_in, const int* in_sizes, int n_in,
                              void* d_out, int out_size)
{
    const float* x    = (const float*)d_in[0];
    const float* ck   = (const float*)d_in[1];
    const float* cb   = (const float*)d_in[2];
    const float* Wi   = (const float*)d_in[3];
    const float* Wf   = (const float*)d_in[4];
    const float* Wz   = (const float*)d_in[5];
    const float* Wo   = (const float*)d_in[6];
    const float* R    = (const float*)d_in[7];
    const float* cbi  = (const float*)d_in[8];
    const float* gns  = (const float*)d_in[9];
    float* out = (float*)d_out;

    conv_swish_kernel<<<(B_ * S_ * D_ + 255) / 256, 256>>>(x, ck, cb);
    gate_gemm_kernel<<<dim3(DH_ / 64, (B_ * S_) / 64, 16), 256>>>(x, Wi, Wf, Wz, Wo);
    slstm_scan_kernel<<<16 * CL_, 192>>>(R, cbi);
    mh_layernorm_kernel<<<B_ * S_ * NH_, 192>>>(gns, out);
}

// round 12
// speedup vs baseline: 1.6825x; 1.6825x over previous
#include <cuda_runtime.h>
#include <cstdint>

// Problem constants
#define B_   4
#define S_   2048
#define D_   768
#define NH_  4
#define DH_  192
#define KC_  4
#define EPS_ 1e-5f

// Scratch (device globals; no allocation allowed)
__device__ float g_xconv[B_ * S_ * D_];            // 25 MB
__device__ float g_G[4 * B_ * S_ * D_];            // 100 MB
__device__ float g_yraw[B_ * S_ * D_];             // 25 MB

// ---------------------------------------------------------------------------
// Kernel 1: causal depthwise conv1d + swish
// ---------------------------------------------------------------------------
__global__ __launch_bounds__(256) void conv_swish_kernel(
    const float* __restrict__ x, const float* __restrict__ ck,
    const float* __restrict__ cb)
{
    int idx = blockIdx.x * 256 + threadIdx.x;
    if (idx >= B_ * S_ * D_) return;
    int d = idx % D_;
    int s = (idx / D_) & (S_ - 1);
    float acc = cb[d];
    const float* xp = x + idx;
#pragma unroll
    for (int j = 0; j < KC_; j++) {
        int ss = s - (KC_ - 1) + j;
        if (ss >= 0) acc += ck[j * D_ + d] * xp[(j - (KC_ - 1)) * D_];
    }
    g_xconv[idx] = acc / (1.f + __expf(-acc));
}

// ---------------------------------------------------------------------------
// Kernel 2: headwise gate GEMMs (known good).
// ---------------------------------------------------------------------------
__global__ __launch_bounds__(256) void gate_gemm_kernel(
    const float* __restrict__ x,
    const float* __restrict__ Wi, const float* __restrict__ Wf,
    const float* __restrict__ Wz, const float* __restrict__ Wo)
{
    const int gz = blockIdx.z;
    const int g = gz >> 2;
    const int h = gz & 3;
    const float* A = (g < 2) ? g_xconv : x;
    const float* W = (g == 0) ? Wi : (g == 1) ? Wf : (g == 2) ? Wz : Wo;
    W += (size_t)h * DH_ * DH_;

    const int n0 = blockIdx.x * 64;
    const int m0 = blockIdx.y * 64;

    __shared__ __align__(16) float As[16][68];  // [k][m]
    __shared__ __align__(16) float Bs[16][68];  // [k][e]

    const int tid = threadIdx.x;
    const int tn = tid & 15;
    const int tm = tid >> 4;

    float acc[4][4] = {};

    for (int k0 = 0; k0 < DH_; k0 += 16) {
#pragma unroll
        for (int i = 0; i < 4; i++) {
            int lin = tid + i * 256;
            int r = lin >> 4, cc = lin & 15;
            As[cc][r] = A[(size_t)(m0 + r) * D_ + h * DH_ + k0 + cc];
        }
#pragma unroll
        for (int i = 0; i < 4; i++) {
            int lin = tid + i * 256;
            int r = lin >> 6, cc = lin & 63;
            Bs[r][cc] = W[(size_t)(k0 + r) * DH_ + n0 + cc];
        }
        __syncthreads();
#pragma unroll
        for (int kk = 0; kk < 16; kk++) {
            float4 av = *(const float4*)&As[kk][tm * 4];
            float4 bv = *(const float4*)&Bs[kk][tn * 4];
            acc[0][0] += av.x * bv.x; acc[0][1] += av.x * bv.y;
            acc[0][2] += av.x * bv.z; acc[0][3] += av.x * bv.w;
            acc[1][0] += av.y * bv.x; acc[1][1] += av.y * bv.y;
            acc[1][2] += av.y * bv.z; acc[1][3] += av.y * bv.w;
            acc[2][0] += av.z * bv.x; acc[2][1] += av.z * bv.y;
            acc[2][2] += av.z * bv.z; acc[2][3] += av.z * bv.w;
            acc[3][0] += av.w * bv.x; acc[3][1] += av.w * bv.y;
            acc[3][2] += av.w * bv.z; acc[3][3] += av.w * bv.w;
        }
        __syncthreads();
    }

#pragma unroll
    for (int i = 0; i < 4; i++) {
        int mm = m0 + tm * 4 + i;
        int bb = mm >> 11;
        int ss = mm & (S_ - 1);
        float4 v = make_float4(acc[i][0], acc[i][1], acc[i][2], acc[i][3]);
        *(float4*)&g_G[((size_t)(bb * NH_ + h) * S_ + ss) * D_ + g * DH_ + n0 + tn * 4] = v;
    }
}

// ---------------------------------------------------------------------------
// Kernel 3: sequential sLSTM scan — 4-CTA cluster + st.async transactions
// (R8 protocol) with gate-interleaved lane mapping (no in-loop barrier).
//
// One cluster of 4 CTAs per (b,h) chain; CTA rank q owns e in [48q, 48q+48).
// 192 threads: thread tid -> gate gp = tid&3, local column el = tid>>2,
// global column ecol = 48q + el. The 4 gates of a column sit in 4 adjacent
// lanes of one warp: pre-activations exchanged via width-4 shfl (no smem, no
// __syncthreads). Gate tail replicated in the 4 lanes (identical fp ops ->
// deterministic); lane gp sends hn to rank gp via ONE st.async (4B tx).
// Each CTA's mbarrier (count=1) expects 4 ranks x 48 x 4B = 768B per phase;
// tid0 arms expect_tx right after passing the wait.
// WAR safety: phase p completion requires EVERY thread's phase-p send, and
// each send data-depends on that thread's full read of hbuf[p&1]; so all
// reads of a buffer complete before any next-phase store can land in it.
// Phases cannot run away: each needs tid0's single arrival, and all warps
// wait on the same barrier every step.
// ---------------------------------------------------------------------------
__device__ __forceinline__ uint32_t smem_u32(const void* p) {
    uint32_t a;
    asm("{ .reg .u64 t; cvta.to.shared.u64 t, %1; cvt.u32.u64 %0, t; }"
        : "=r"(a) : "l"(p));
    return a;
}

#define CLUSTER_SYNC_() do { \
    asm volatile("barrier.cluster.arrive.aligned;" ::: "memory"); \
    asm volatile("barrier.cluster.wait.aligned;"   ::: "memory"); \
} while (0)

__device__ __forceinline__ void mbar_wait_acq(uint32_t addr, uint32_t parity) {
    uint32_t done;
    asm volatile("{\n\t.reg .pred p;\n\t"
        "mbarrier.try_wait.parity.acquire.cluster.shared::cta.b64 p, [%1], %2;\n\t"
        "selp.b32 %0, 1, 0, p;\n\t}"
        : "=r"(done) : "r"(addr), "r"(parity) : "memory");
    if (!done) {
        asm volatile("{\n\t.reg .pred P1;\n\t"
            "WL_%=:\n\t"
            "mbarrier.try_wait.parity.acquire.cluster.shared::cta.b64 P1, [%0], %1, 0x989680;\n\t"
            "@P1 bra.uni WD_%=;\n\t"
            "bra.uni WL_%=;\n\t"
            "WD_%=:\n\t}"
            :: "r"(addr), "r"(parity) : "memory");
    }
}

#define TX_BYTES_ (DH_ * 4)   // 768: full h per phase

__global__ void __cluster_dims__(4, 1, 1) __launch_bounds__(192, 1)
slstm_scan_kernel(const float* __restrict__ R, const float* __restrict__ cell_bias)
{
    __shared__ __align__(16) float hbuf[2][DH_];
    __shared__ __align__(8) unsigned long long mbar;

    const int tid   = threadIdx.x;
    const int chain = blockIdx.x >> 2;      // 0..15
    const int q     = blockIdx.x & 3;       // cluster rank
    const int b     = chain >> 2;
    const int h     = chain & 3;
    const int gp    = tid & 3;              // gate of this lane
    const int el    = tid >> 2;             // local column 0..47
    const int ecol  = q * 48 + el;          // global column

    // Load this thread's R column as 96 packed f32x2 pairs (over d).
    unsigned long long r2[96];
    {
        const float* Rcol = R + ((size_t)(gp * NH_ + h)) * DH_ * DH_ + ecol;
#pragma unroll
        for (int j = 0; j < 96; j++) {
            float lo = Rcol[(2 * j) * DH_];
            float hi = Rcol[(2 * j + 1) * DH_];
            asm("mov.b64 %0, {%1, %2};" : "=l"(r2[j]) : "f"(lo), "f"(hi));
        }
    }
    const float cbias = cell_bias[gp * D_ + h * DH_ + ecol];

    const float* Gp = g_G + ((size_t)(b * NH_ + h)) * S_ * D_ + gp * DH_ + ecol;
    float* Yp = g_yraw + (size_t)b * S_ * D_ + h * DH_ + ecol;

    const uint32_t hb_base = smem_u32(&hbuf[0][0]);
    const uint32_t mb_addr = smem_u32(&mbar);

    hbuf[0][tid] = 0.f;
    hbuf[1][tid] = 0.f;
    if (tid == 0) {
        asm volatile("mbarrier.init.shared.b64 [%0], %1;"
                     :: "r"(mb_addr), "r"(1) : "memory");
        // Arm phase 0 before anyone can send (pre-cluster.sync).
        asm volatile("mbarrier.arrive.expect_tx.shared.b64 _, [%0], %1;"
                     :: "r"(mb_addr), "r"(TX_BYTES_) : "memory");
    }
    __syncthreads();
    CLUSTER_SYNC_();   // hbuf + armed mbarrier visible cluster-wide (once)

    // Remote hbuf/mbarrier addresses for this lane's destination rank (gp).
    uint32_t rhb_s, rmb_s;
    asm("mapa.shared::cluster.u32 %0, %1, %2;" : "=r"(rhb_s) : "r"(hb_base), "r"(gp));
    asm("mapa.shared::cluster.u32 %0, %1, %2;" : "=r"(rmb_s) : "r"(mb_addr), "r"(gp));

    float c = 0.f, n = 0.f, m = 0.f;

    // 2-deep G prefetch ring.
    float gbuf0 = Gp[0];
    float gbuf1 = Gp[D_];

    for (int t = 0; t < S_; ++t) {
        float gnn = (t + 2 < S_) ? Gp[(size_t)(t + 2) * D_] : 0.f;

        if (t > 0) {
            // Wait for phase t-1 (all 768B of h(t) delivered).
            mbar_wait_acq(mb_addr, (uint32_t)((t - 1) & 1));
            // Arm phase t (single arrival).
            if (tid == 0 && t <= S_ - 2) {
                asm volatile("mbarrier.arrive.expect_tx.shared.b64 _, [%0], %1;"
                             :: "r"(mb_addr), "r"(TX_BYTES_) : "memory");
            }
        }

        // Recurrent matvec: rec[ecol] = sum_d h[d] * R[gp][h][d][ecol]
        const ulonglong2* h128 = (const ulonglong2*)hbuf[t & 1];
        unsigned long long a[4] = {0ull, 0ull, 0ull, 0ull};
#pragma unroll
        for (int jj = 0; jj < 48; jj++) {
            ulonglong2 hv = h128[jj];
            asm("fma.rn.f32x2 %0, %1, %2, %0;"
                : "+l"(a[(2 * jj) & 3]) : "l"(hv.x), "l"(r2[2 * jj]));
            asm("fma.rn.f32x2 %0, %1, %2, %0;"
                : "+l"(a[(2 * jj + 1) & 3]) : "l"(hv.y), "l"(r2[2 * jj + 1]));
        }
        float l0, h0, l1, h1, l2, h2, l3, h3;
        asm("mov.b64 {%0, %1}, %2;" : "=f"(l0), "=f"(h0) : "l"(a[0]));
        asm("mov.b64 {%0, %1}, %2;" : "=f"(l1), "=f"(h1) : "l"(a[1]));
        asm("mov.b64 {%0, %1}, %2;" : "=f"(l2), "=f"(h2) : "l"(a[2]));
        asm("mov.b64 {%0, %1}, %2;" : "=f"(l3), "=f"(h3) : "l"(a[3]));
        float rec = ((l0 + h0) + (l1 + h1)) + ((l2 + h2) + (l3 + h3));

        // Per-gate nonlinearity in this lane (z -> tanh, o -> sigmoid).
        float pre = rec + gbuf0 + cbias;
        float sv;
        if (gp == 2)      sv = tanhf(pre);
        else if (gp == 3) sv = __fdividef(1.f, 1.f + __expf(-pre));
        else              sv = pre;

        // Exchange the 4 gate values within the 4-lane group (width-4 shfl).
        float i_ = __shfl_sync(0xFFFFFFFFu, sv, 0, 4);
        float f_ = __shfl_sync(0xFFFFFFFFu, sv, 1, 4);
        float tz = __shfl_sync(0xFFFFFFFFu, sv, 2, 4);
        float so = __shfl_sync(0xFFFFFFFFu, sv, 3, 4);

        // Replicated gate tail (identical ops in the 4 lanes -> deterministic).
        float mn = fmaxf(f_ + m, i_);
        float ia = __expf(i_ - mn);
        float fa = __expf(f_ + m - mn);
        c = fa * c + ia * tz;
        n = fa * n + ia;
        m = mn;
        float hn = __fdividef(c, n) * so;

        if (gp == 0) Yp[(size_t)t * D_] = hn;

        if (t < S_ - 1) {
            // Lane gp sends hn[ecol] to rank gp's hbuf[(t+1)&1][ecol] (4B tx).
            uint32_t off = (uint32_t)((((t + 1) & 1) * DH_ + ecol) * 4);
            uint32_t hv; asm("mov.b32 %0, %1;" : "=r"(hv) : "f"(hn));
            asm volatile(
                "st.async.shared::cluster.mbarrier::complete_tx::bytes.b32 [%0], %1, [%2];"
                :: "r"(rhb_s + off), "r"(hv), "r"(rmb_s) : "memory");
        }

        gbuf0 = gbuf1;
        gbuf1 = gnn;
    }

    CLUSTER_SYNC_();   // no CTA exits while peers might still address its smem
}

// ---------------------------------------------------------------------------
// Kernel 4: multi-head layernorm over DH per (b,s,h) row.
// ---------------------------------------------------------------------------
__global__ __launch_bounds__(192) void mh_layernorm_kernel(
    const float* __restrict__ gn_scale, float* __restrict__ out)
{
    const int h  = blockIdx.x & (NH_ - 1);
    const int bs = blockIdx.x >> 2;
    const int base = bs * D_ + h * DH_;
    const int tid = threadIdx.x;

    float v = g_yraw[base + tid];
    float s1 = v, s2 = v * v;
#pragma unroll
    for (int o = 16; o; o >>= 1) {
        s1 += __shfl_xor_sync(0xFFFFFFFFu, s1, o);
        s2 += __shfl_xor_sync(0xFFFFFFFFu, s2, o);
    }
    __shared__ float r1[6], r2s[6];
    int w = tid >> 5;
    if ((tid & 31) == 0) { r1[w] = s1; r2s[w] = s2; }
    __syncthreads();
    float t1 = 0.f, t2 = 0.f;
#pragma unroll
    for (int i = 0; i < 6; i++) { t1 += r1[i]; t2 += r2s[i]; }
    const float inv = 1.f / (float)DH_;
    float mu  = t1 * inv;
    float var = t2 * inv - mu * mu;
    float rs  = rsqrtf(var + EPS_);
    out[base + tid] = (v - mu) * rs * gn_scale[h * DH_ + tid];
}

// ---------------------------------------------------------------------------
// Launch
// ---------------------------------------------------------------------------
extern "C" void kernel_launch(void* const* d_in, const int* in_sizes, int n_in,
                              void* d_out, int out_size)
{
    const float* x    = (const float*)d_in[0];
    const float* ck   = (const float*)d_in[1];
    const float* cb   = (const float*)d_in[2];
    const float* Wi   = (const float*)d_in[3];
    const float* Wf   = (const float*)d_in[4];
    const float* Wz   = (const float*)d_in[5];
    const float* Wo   = (const float*)d_in[6];
    const float* R    = (const float*)d_in[7];
    const float* cbi  = (const float*)d_in[8];
    const float* gns  = (const float*)d_in[9];
    float* out = (float*)d_out;

    conv_swish_kernel<<<(B_ * S_ * D_ + 255) / 256, 256>>>(x, ck, cb);
    gate_gemm_kernel<<<dim3(DH_ / 64, (B_ * S_) / 64, 16), 256>>>(x, Wi, Wf, Wz, Wo);
    slstm_scan_kernel<<<64, 192>>>(R, cbi);
    mh_layernorm_kernel<<<B_ * S_ * NH_, 192>>>(gns, out);
}